// round 13
// baseline (speedup 1.0000x reference)
#include <cuda_runtime.h>
#include <math.h>

#define BN    8192
#define NINPC 256
#define NHIDC 1024

// ---------------------------------------------------------------------------
// Scratch (device globals)
// ---------------------------------------------------------------------------
__device__ float g_kk  [BN * 64];
__device__ float g_v1  [BN * 512];        // tf32-rounded v1
__device__ float g_q   [BN * 512];
__device__ float g_s   [BN * 8];
__device__ float g_mask[BN * 8];
__device__ float g_gx  [BN * 8 * 384];    // GRU input gates (b,z,384)
__device__ float g_hn  [BN * 1024];       // exact hx_new (pre-att)
__device__ float g_hnr [BN * 1024];       // tf32-rounded hx_new
__device__ float g_qkv [BN * 8 * 192];    // fused q2|k2|v2
__device__ float g_o   [BN * 512];        // attention-2 output (tf32-rounded)
// rounded weights
__device__ float g_wv1r[256 * 512];
__device__ float g_wir [8 * 512 * 384];
__device__ float g_whr [8 * 128 * 384];
__device__ float g_w2r [8 * 128 * 192];
__device__ float g_gf  [64 * 256];        // interleaved [gate|fc] weights

__device__ __forceinline__ unsigned f2tf32(float x) {
    unsigned u;
    asm("cvt.rna.tf32.f32 %0, %1;" : "=r"(u) : "f"(x));
    return u;
}
__device__ __forceinline__ unsigned smem_u32(const void* p) {
    unsigned a;
    asm("{ .reg .u64 t; cvta.to.shared.u64 t, %1; cvt.u32.u64 %0, t; }"
        : "=r"(a) : "l"(p));
    return a;
}
#define CP16(dst, src) \
    asm volatile("cp.async.cg.shared.global [%0], [%1], 16;" :: "r"(dst), "l"(src))
#define CP_COMMIT() asm volatile("cp.async.commit_group;")
#define MMA_TF32(acc, a0, a1, a2, a3, b0, b1) \
    asm volatile( \
        "mma.sync.aligned.m16n8k8.row.col.f32.tf32.tf32.f32 " \
        "{%0,%1,%2,%3}, {%4,%5,%6,%7}, {%8,%9}, {%0,%1,%2,%3};" \
        : "+f"((acc)[0]), "+f"((acc)[1]), "+f"((acc)[2]), "+f"((acc)[3]) \
        : "r"(a0), "r"(a1), "r"(a2), "r"(a3), "r"(b0), "r"(b1))

// ---------------------------------------------------------------------------
// Elementwise tf32 rounding copy (weights only now)
// ---------------------------------------------------------------------------
__global__ void round_tf32(const float* __restrict__ src, float* __restrict__ dst, int n4)
{
    int i = blockIdx.x * blockDim.x + threadIdx.x;
    if (i < n4) {
        float4 v = ((const float4*)src)[i];
        v.x = __uint_as_float(f2tf32(v.x));
        v.y = __uint_as_float(f2tf32(v.y));
        v.z = __uint_as_float(f2tf32(v.z));
        v.w = __uint_as_float(f2tf32(v.w));
        ((float4*)dst)[i] = v;
    }
}

// Concatenate Wq2|Wk2|Wv2 (each (8,128,64)) -> (8,128,192), tf32-rounded
__global__ void build_w2(const float* __restrict__ q, const float* __restrict__ k,
                         const float* __restrict__ v, float* __restrict__ dst)
{
    int i = blockIdx.x * blockDim.x + threadIdx.x;
    if (i >= 8 * 128 * 192) return;
    int c = i % 192, r = (i / 192) % 128, z = i / (192 * 128);
    const float* src = (c < 64) ? q : ((c < 128) ? k : v);
    dst[i] = __uint_as_float(f2tf32(src[z * 8192 + r * 64 + (c & 63)]));
}

// Interleave gate_w/fc_w (64x128 each) -> (64, 256): cols (2n, 2n+1) = (gw, fw)
__global__ void build_gf(const float* __restrict__ gw, const float* __restrict__ fw,
                         float* __restrict__ dst)
{
    int i = blockIdx.x * blockDim.x + threadIdx.x;
    if (i >= 64 * 128) return;
    int k = i >> 7, n = i & 127;
    dst[k * 256 + 2 * n]     = __uint_as_float(f2tf32(gw[k * 128 + n]));
    dst[k * 256 + 2 * n + 1] = __uint_as_float(f2tf32(fw[k * 128 + n]));
}

// ---------------------------------------------------------------------------
// tf32 mma.sync GEMM, CTA tile 128 x NT, K-chunk 32, 2-stage cp.async.
//   A[z*aZoff + m*lda + k],  B[z*bZstr + k*ldb + n],  C[z*cZoff + m*ldc + n]
// CVTA: round A fragments in-register (A unrounded fp32 in gmem).
// MODE 0: C=acc  1: C=sv[m*8+z]*acc+bias  2: C=acc+bias  3: C=round(acc)
// ---------------------------------------------------------------------------
template<int NT, int WARPS_M, int MODE, bool CVTA>
__global__ void __launch_bounds__(256)
gemm_tf32(const float* __restrict__ A, int lda, int aZoff,
          const float* __restrict__ B, int ldb, long bZstr,
          float* __restrict__ C, int ldc, long cZoff, int K,
          const float* __restrict__ sv, const float* __restrict__ bias, int biasLd)
{
    constexpr int ASTR = 36;
    constexpr int BSTR = NT + 4;
    constexpr int STAGE = 128 * ASTR + 32 * BSTR;
    constexpr int WM = 128 / WARPS_M;
    constexpr int MF = WM / 16;
    constexpr int NF = 4;
    constexpr int BITER = NT / 32;

    extern __shared__ unsigned dsm[];
    const unsigned sbase = smem_u32(dsm);

    const int tid = threadIdx.x, lane = tid & 31, wid = tid >> 5;
    const int warpM = wid % WARPS_M, warpN = wid / WARPS_M;
    const int m0 = blockIdx.x * 128, n0 = blockIdx.y * NT, z = blockIdx.z;
    const float* Az = A + (long)z * aZoff;
    const float* Bz = B + (long)z * bZstr;
    const int lr = lane >> 2, lc = lane & 3;

    float acc[MF][NF][4];
#pragma unroll
    for (int i = 0; i < MF; i++)
#pragma unroll
        for (int j = 0; j < NF; j++)
#pragma unroll
            for (int e = 0; e < 4; e++) acc[i][j][e] = 0.f;

    auto load_stage = [&](int buf, int k0) {
        const unsigned base = sbase + buf * STAGE * 4;
        const int ar = tid >> 3, ac4 = (tid & 7) * 4;
#pragma unroll
        for (int i = 0; i < 4; i++) {
            const int row = i * 32 + ar;
            CP16(base + (row * ASTR + ac4) * 4,
                 Az + (long)(m0 + row) * lda + k0 + ac4);
        }
        const unsigned bb = base + 128 * ASTR * 4;
#pragma unroll
        for (int i = 0; i < BITER; i++) {
            const int idx = i * 256 + tid;
            const int row = idx / (NT / 4), c4 = (idx % (NT / 4)) * 4;
            CP16(bb + (row * BSTR + c4) * 4,
                 Bz + (long)(k0 + row) * ldb + n0 + c4);
        }
        CP_COMMIT();
    };

    const int NITER = K / 32;
    load_stage(0, 0);

    for (int it = 0; it < NITER; it++) {
        if (it + 1 < NITER) {
            load_stage((it + 1) & 1, (it + 1) * 32);
            asm volatile("cp.async.wait_group 1;");
        } else {
            asm volatile("cp.async.wait_group 0;");
        }
        __syncthreads();

        const unsigned* Au = dsm + (it & 1) * STAGE;
        const unsigned* Bu = Au + 128 * ASTR;
#pragma unroll
        for (int s = 0; s < 4; s++) {
            const int kc = s * 8;
            unsigned af[MF][4];
#pragma unroll
            for (int mf = 0; mf < MF; mf++) {
                const int r0 = warpM * WM + mf * 16 + lr;
                unsigned r_[4];
                r_[0] = Au[(r0)     * ASTR + kc + lc];
                r_[1] = Au[(r0 + 8) * ASTR + kc + lc];
                r_[2] = Au[(r0)     * ASTR + kc + lc + 4];
                r_[3] = Au[(r0 + 8) * ASTR + kc + lc + 4];
#pragma unroll
                for (int e = 0; e < 4; e++)
                    af[mf][e] = CVTA ? f2tf32(__uint_as_float(r_[e])) : r_[e];
            }
            unsigned bf[NF][2];
#pragma unroll
            for (int nf = 0; nf < NF; nf++) {
                const int cb = warpN * 32 + nf * 8 + lr;
                bf[nf][0] = Bu[(kc + lc)     * BSTR + cb];
                bf[nf][1] = Bu[(kc + lc + 4) * BSTR + cb];
            }
#pragma unroll
            for (int mf = 0; mf < MF; mf++)
#pragma unroll
                for (int nf = 0; nf < NF; nf++)
                    MMA_TF32(acc[mf][nf], af[mf][0], af[mf][1], af[mf][2], af[mf][3],
                             bf[nf][0], bf[nf][1]);
        }
        __syncthreads();
    }

    float* Cz = C + (long)z * cZoff;
    const float* bz = bias ? (bias + (long)z * biasLd) : nullptr;
#pragma unroll
    for (int mf = 0; mf < MF; mf++) {
        const int r = m0 + warpM * WM + mf * 16 + lr;
        float s0 = 1.f, s1 = 1.f;
        if (MODE == 1) { s0 = sv[(long)r * 8 + z]; s1 = sv[(long)(r + 8) * 8 + z]; }
#pragma unroll
        for (int nf = 0; nf < NF; nf++) {
            const int c = n0 + warpN * 32 + nf * 8 + lc * 2;
            float v0 = acc[mf][nf][0], v1 = acc[mf][nf][1];
            float v2 = acc[mf][nf][2], v3 = acc[mf][nf][3];
            if (MODE == 1) {
                v0 = s0 * v0 + bz[c]; v1 = s0 * v1 + bz[c + 1];
                v2 = s1 * v2 + bz[c]; v3 = s1 * v3 + bz[c + 1];
            } else if (MODE == 2) {
                v0 += bz[c]; v1 += bz[c + 1];
                v2 += bz[c]; v3 += bz[c + 1];
            } else if (MODE == 3) {
                v0 = __uint_as_float(f2tf32(v0)); v1 = __uint_as_float(f2tf32(v1));
                v2 = __uint_as_float(f2tf32(v2)); v3 = __uint_as_float(f2tf32(v3));
            }
            *(float2*)(Cz + (long)r * ldc + c)       = make_float2(v0, v1);
            *(float2*)(Cz + (long)(r + 8) * ldc + c) = make_float2(v2, v3);
        }
    }
}

// ---------------------------------------------------------------------------
// Fused gh GEMM + GRU.  Per CTA: 32 batch rows, one block z, N=384 (all
// gates), K=128.  gh tile staged in smem; epilogue reads gx/hx, writes hn/hnr.
// warps: 2 (M) x 4 (N=96 each); A fragments rounded in-register from raw hx.
// ---------------------------------------------------------------------------
__global__ void __launch_bounds__(256, 2)
gemm_gru(const float* __restrict__ hx, const float* __restrict__ whr,
         const float* __restrict__ bh)
{
    constexpr int ASTR = 36, BSTR = 388;
    constexpr int STAGE = 32 * ASTR + 32 * BSTR;   // 13568 floats

    extern __shared__ float smf[];
    const unsigned sbase = smem_u32(smf);

    const int tid = threadIdx.x, lane = tid & 31, wid = tid >> 5;
    const int warpM = wid & 1, warpN = wid >> 1;
    const int m0 = blockIdx.x * 32, z = blockIdx.y;
    const float* Az = hx + (long)m0 * 1024 + z * 128;
    const float* Bz = whr + (long)z * (128 * 384);
    const int lr = lane >> 2, lc = lane & 3;

    float acc[12][4];
#pragma unroll
    for (int i = 0; i < 12; i++)
#pragma unroll
        for (int e = 0; e < 4; e++) acc[i][e] = 0.f;

    auto load_stage = [&](int buf, int k0) {
        const unsigned base = sbase + buf * STAGE * 4;
        {   // A: 32 rows x 32 cols, 1 CP16/thread
            const int row = tid >> 3, c4 = (tid & 7) * 4;
            CP16(base + (row * ASTR + c4) * 4, Az + (long)row * 1024 + k0 + c4);
        }
        const unsigned bb = base + 32 * ASTR * 4;
#pragma unroll
        for (int i = 0; i < 12; i++) {   // B: 32 x 384
            const int idx = i * 256 + tid;
            const int row = idx / 96, c4 = (idx % 96) * 4;
            CP16(bb + (row * BSTR + c4) * 4, Bz + (long)(k0 + row) * 384 + c4);
        }
        CP_COMMIT();
    };

    load_stage(0, 0);
    for (int it = 0; it < 4; it++) {
        if (it < 3) {
            load_stage((it + 1) & 1, (it + 1) * 32);
            asm volatile("cp.async.wait_group 1;");
        } else {
            asm volatile("cp.async.wait_group 0;");
        }
        __syncthreads();

        const float* Af = smf + (it & 1) * STAGE;
        const float* Bf = Af + 32 * ASTR;
#pragma unroll
        for (int s = 0; s < 4; s++) {
            const int kc = s * 8;
            const int r0 = warpM * 16 + lr;
            const unsigned a0 = f2tf32(Af[(r0)     * ASTR + kc + lc]);
            const unsigned a1 = f2tf32(Af[(r0 + 8) * ASTR + kc + lc]);
            const unsigned a2 = f2tf32(Af[(r0)     * ASTR + kc + lc + 4]);
            const unsigned a3 = f2tf32(Af[(r0 + 8) * ASTR + kc + lc + 4]);
#pragma unroll
            for (int nf = 0; nf < 12; nf++) {
                const int cb = warpN * 96 + nf * 8 + lr;
                const unsigned b0 = __float_as_uint(Bf[(kc + lc)     * BSTR + cb]);
                const unsigned b1 = __float_as_uint(Bf[(kc + lc + 4) * BSTR + cb]);
                MMA_TF32(acc[nf], a0, a1, a2, a3, b0, b1);
            }
        }
        __syncthreads();
    }

    // stage gh (+bias) tile into smem [32][388]
    const float* bhz = bh + z * 384;
    {
        const int r0 = warpM * 16 + lr;
#pragma unroll
        for (int nf = 0; nf < 12; nf++) {
            const int c0 = warpN * 96 + nf * 8 + lc * 2;
            const float b0 = bhz[c0], b1 = bhz[c0 + 1];
            *(float2*)(smf + (r0)     * BSTR + c0) = make_float2(acc[nf][0] + b0, acc[nf][1] + b1);
            *(float2*)(smf + (r0 + 8) * BSTR + c0) = make_float2(acc[nf][2] + b0, acc[nf][3] + b1);
        }
    }
    __syncthreads();

    // GRU epilogue: 32 rows x 128 cols, float4 per task
    for (int t = tid; t < 1024; t += 256) {
        const int row = t >> 5, e = (t & 31) * 4;
        const long gxb = (long)(m0 + row) * 3072 + z * 384 + e;
        const float4 xr4 = *(const float4*)(g_gx + gxb);
        const float4 xz4 = *(const float4*)(g_gx + gxb + 128);
        const float4 xn4 = *(const float4*)(g_gx + gxb + 256);
        const float4 hr4 = *(const float4*)(smf + row * BSTR + e);
        const float4 hz4 = *(const float4*)(smf + row * BSTR + e + 128);
        const float4 hn4 = *(const float4*)(smf + row * BSTR + e + 256);
        const long hb = (long)(m0 + row) * 1024 + z * 128 + e;
        const float4 h4 = *(const float4*)(hx + hb);
        float4 o4, orr;
        {
            const float xr[4] = {xr4.x, xr4.y, xr4.z, xr4.w};
            const float xz[4] = {xz4.x, xz4.y, xz4.z, xz4.w};
            const float xn[4] = {xn4.x, xn4.y, xn4.z, xn4.w};
            const float hr[4] = {hr4.x, hr4.y, hr4.z, hr4.w};
            const float hz[4] = {hz4.x, hz4.y, hz4.z, hz4.w};
            const float hn[4] = {hn4.x, hn4.y, hn4.z, hn4.w};
            const float hh[4] = {h4.x, h4.y, h4.z, h4.w};
            float o[4], orf[4];
#pragma unroll
            for (int j = 0; j < 4; j++) {
                const float r  = 1.f / (1.f + expf(-(xr[j] + hr[j])));
                const float zz = 1.f / (1.f + expf(-(xz[j] + hz[j])));
                const float n  = tanhf(xn[j] + r * hn[j]);
                o[j]   = (1.f - zz) * n + zz * hh[j];
                orf[j] = __uint_as_float(f2tf32(o[j]));
            }
            o4  = make_float4(o[0], o[1], o[2], o[3]);
            orr = make_float4(orf[0], orf[1], orf[2], orf[3]);
        }
        *(float4*)(g_hn + hb)  = o4;
        *(float4*)(g_hnr + hb) = orr;
    }
}

// ---------------------------------------------------------------------------
// Final tf32 dual GEMM with fused gating / masked blend.
// A = g_o (65536 x 64), B = g_gf (64 x 256, (2n,2n+1)=(gate,fc)).
// CTA: M=128, NT=64 (32 output cols).  warps 4(M) x 2(N).
// ---------------------------------------------------------------------------
__global__ void __launch_bounds__(256)
final_tc(const float* __restrict__ gb, const float* __restrict__ fb,
         const float* __restrict__ hx,
         float* __restrict__ outHx, float* __restrict__ outMask)
{
    constexpr int ASTR = 36, BSTR = 68;
    constexpr int STAGE = 128 * ASTR + 32 * BSTR;   // 6784 floats

    extern __shared__ unsigned dsm[];
    const unsigned sbase = smem_u32(dsm);

    const int tid = threadIdx.x, lane = tid & 31, wid = tid >> 5;
    const int warpM = wid & 3, warpN = wid >> 2;
    const int m0 = blockIdx.x * 128, n0 = blockIdx.y * 64;
    const int lr = lane >> 2, lc = lane & 3;

    float acc[2][4][4];
#pragma unroll
    for (int i = 0; i < 2; i++)
#pragma unroll
        for (int j = 0; j < 4; j++)
#pragma unroll
            for (int e = 0; e < 4; e++) acc[i][j][e] = 0.f;

    auto load_stage = [&](int buf, int k0) {
        const unsigned base = sbase + buf * STAGE * 4;
        const int ar = tid >> 3, ac4 = (tid & 7) * 4;
#pragma unroll
        for (int i = 0; i < 4; i++) {
            const int row = i * 32 + ar;
            CP16(base + (row * ASTR + ac4) * 4,
                 g_o + (long)(m0 + row) * 64 + k0 + ac4);
        }
        const unsigned bb = base + 128 * ASTR * 4;
#pragma unroll
        for (int i = 0; i < 2; i++) {
            const int idx = i * 256 + tid;
            const int row = idx >> 4, c4 = (idx & 15) * 4;
            CP16(bb + (row * BSTR + c4) * 4,
                 g_gf + (long)(k0 + row) * 256 + n0 + c4);
        }
        CP_COMMIT();
    };

    load_stage(0, 0);
    for (int it = 0; it < 2; it++) {
        if (it == 0) {
            load_stage(1, 32);
            asm volatile("cp.async.wait_group 1;");
        } else {
            asm volatile("cp.async.wait_group 0;");
        }
        __syncthreads();
        const unsigned* Au = dsm + it * STAGE;
        const unsigned* Bu = Au + 128 * ASTR;
#pragma unroll
        for (int s = 0; s < 4; s++) {
            const int kc = s * 8;
            unsigned af[2][4];
#pragma unroll
            for (int mf = 0; mf < 2; mf++) {
                const int r0 = warpM * 32 + mf * 16 + lr;
                af[mf][0] = Au[(r0)     * ASTR + kc + lc];
                af[mf][1] = Au[(r0 + 8) * ASTR + kc + lc];
                af[mf][2] = Au[(r0)     * ASTR + kc + lc + 4];
                af[mf][3] = Au[(r0 + 8) * ASTR + kc + lc + 4];
            }
#pragma unroll
            for (int nf = 0; nf < 4; nf++) {
                const int cb = warpN * 32 + nf * 8 + lr;
                const unsigned b0 = Bu[(kc + lc)     * BSTR + cb];
                const unsigned b1 = Bu[(kc + lc + 4) * BSTR + cb];
#pragma unroll
                for (int mf = 0; mf < 2; mf++)
                    MMA_TF32(acc[mf][nf], af[mf][0], af[mf][1], af[mf][2], af[mf][3], b0, b1);
            }
        }
        __syncthreads();
    }

#pragma unroll
    for (int mf = 0; mf < 2; mf++) {
        const int r = m0 + warpM * 32 + mf * 16 + lr;
        const float ma = g_mask[r], mb = g_mask[r + 8];
#pragma unroll
        for (int nf = 0; nf < 4; nf++) {
            const int c = n0 + warpN * 32 + nf * 8 + lc * 2;
            const int n = c >> 1;
            const float gbv = gb[n], fbv = fb[n];
            {
                const float u = 1.f / (1.f + expf(-(acc[mf][nf][0] + gbv)));
                const float t = tanhf(acc[mf][nf][1] + fbv);
                const long a = (long)r * 128 + n;
                const float h2 = g_hn[a] + u * t;
                outHx[a]   = ma * h2 + (1.f - ma) * hx[a];
                outMask[a] = ma;
            }
            {
                const float u = 1.f / (1.f + expf(-(acc[mf][nf][2] + gbv)));
                const float t = tanhf(acc[mf][nf][3] + fbv);
                const long a = (long)(r + 8) * 128 + n;
                const float h2 = g_hn[a] + u * t;
                outHx[a]   = mb * h2 + (1.f - mb) * hx[a];
                outMask[a] = mb;
            }
        }
    }
}

// ---------------------------------------------------------------------------
// fp32 64x64 tiled GEMM (exact paths: kk, q)
// ---------------------------------------------------------------------------
__global__ void gemm_tile(const float* __restrict__ A, int lda, int aZoff,
                          const float* __restrict__ Bm, int ldb, long bZstr,
                          float* __restrict__ C, int ldc, int cZoff, int K)
{
    __shared__ float As[16][68];
    __shared__ float Bs[16][64];

    const int z = blockIdx.z;
    const float* Az = A + (long)z * aZoff;
    const float* Bz = Bm + (long)z * bZstr;
    float*       Cz = C + (long)z * cZoff;

    const int m0 = blockIdx.y * 64, n0 = blockIdx.x * 64;
    const int tid = threadIdx.x;
    const int tx = tid & 15, ty = tid >> 4;
    const int arow = tid >> 2, ak = (tid & 3) << 2;
    const int bk = tid >> 4,  bn = (tid & 15) << 2;

    float acc[4][4] = {};
    for (int k0 = 0; k0 < K; k0 += 16) {
        float4 a4 = *(const float4*)(Az + (long)(m0 + arow) * lda + k0 + ak);
        float4 b4 = *(const float4*)(Bz + (long)(k0 + bk) * ldb + n0 + bn);
        __syncthreads();
        As[ak + 0][arow] = a4.x; As[ak + 1][arow] = a4.y;
        As[ak + 2][arow] = a4.z; As[ak + 3][arow] = a4.w;
        *(float4*)&Bs[bk][bn] = b4;
        __syncthreads();
#pragma unroll
        for (int kk = 0; kk < 16; kk++) {
            float4 av = *(const float4*)&As[kk][ty * 4];
            float4 bv = *(const float4*)&Bs[kk][tx * 4];
            float a_[4] = {av.x, av.y, av.z, av.w};
            float b_[4] = {bv.x, bv.y, bv.z, bv.w};
#pragma unroll
            for (int i = 0; i < 4; i++)
#pragma unroll
                for (int j = 0; j < 4; j++)
                    acc[i][j] += a_[i] * b_[j];
        }
    }
#pragma unroll
    for (int i = 0; i < 4; i++)
        *(float4*)(Cz + (long)(m0 + ty * 4 + i) * ldc + n0 + tx * 4) =
            make_float4(acc[i][0], acc[i][1], acc[i][2], acc[i][3]);
}

// ---------------------------------------------------------------------------
// score / mask: one warp per batch row (exact fp32, rank-sensitive).
// lane = 4*k + p; p-quarter of the 64-dot, xor-tree reduce, rank via shfl.
// ---------------------------------------------------------------------------
__global__ void score_mask_kernel()
{
    const int b = (blockIdx.x * blockDim.x + threadIdx.x) >> 5;
    const int lane = threadIdx.x & 31;
    const int k = lane >> 2, p = lane & 3;

    const float4* q4 = (const float4*)(g_q + (long)b * 512 + k * 64 + p * 16);
    const float4* k4 = (const float4*)(g_kk + (long)b * 64 + p * 16);
    float l = 0.f;
#pragma unroll
    for (int i = 0; i < 4; i++) {
        float4 a = q4[i], c = k4[i];
        l += a.x * c.x + a.y * c.y + a.z * c.z + a.w * c.w;
    }
    l += __shfl_xor_sync(0xFFFFFFFFu, l, 1);
    l += __shfl_xor_sync(0xFFFFFFFFu, l, 2);
    l *= 0.125f;

    int cnt = 0;
#pragma unroll
    for (int j = 0; j < 8; j++) {
        float lj = __shfl_sync(0xFFFFFFFFu, l, (j << 2) | p);
        if (lj < l || (lj == l && j < k)) cnt++;
    }
    if (p == 0) {
        g_mask[b * 8 + k] = (cnt < 4) ? 0.f : 1.f;
        g_s[b * 8 + k]    = 1.f / (1.f + expf(-l));
    }
}

// ---------------------------------------------------------------------------
// Second attention; output tf32-rounded (feeds final_tc only)
// ---------------------------------------------------------------------------
__global__ void attn2_kernel()
{
    const int b = (blockIdx.x * blockDim.x + threadIdx.x) >> 5;
    const int lane = threadIdx.x & 31;
    const int qb = lane >> 2, h = lane & 3;
    const float* base = g_qkv + (long)b * 1536;

    float4 qv[4];
    const float4* qp = (const float4*)(base + qb * 192 + h * 16);
#pragma unroll
    for (int i = 0; i < 4; i++) qv[i] = qp[i];

    float sc[8];
#pragma unroll
    for (int kb = 0; kb < 8; kb++) {
        const float4* kp = (const float4*)(base + kb * 192 + 64 + h * 16);
        float d = 0.f;
#pragma unroll
        for (int i = 0; i < 4; i++) {
            float4 kv = kp[i];
            d += qv[i].x * kv.x + qv[i].y * kv.y + qv[i].z * kv.z + qv[i].w * kv.w;
        }
        sc[kb] = d * 0.25f;
    }
    float mx = sc[0];
#pragma unroll
    for (int kb = 1; kb < 8; kb++) mx = fmaxf(mx, sc[kb]);
    float den = 0.f;
#pragma unroll
    for (int kb = 0; kb < 8; kb++) { sc[kb] = expf(sc[kb] - mx); den += sc[kb]; }
    const float inv = 1.f / den;

    float4 o[4] = {};
#pragma unroll
    for (int kb = 0; kb < 8; kb++) {
        const float4* vp = (const float4*)(base + kb * 192 + 128 + h * 16);
        const float w = sc[kb] * inv;
#pragma unroll
        for (int i = 0; i < 4; i++) {
            float4 vv = vp[i];
            o[i].x += w * vv.x; o[i].y += w * vv.y;
            o[i].z += w * vv.z; o[i].w += w * vv.w;
        }
    }
    float4* op = (float4*)(g_o + (long)b * 512 + qb * 64 + h * 16);
#pragma unroll
    for (int i = 0; i < 4; i++) {
        float4 v = o[i];
        v.x = __uint_as_float(f2tf32(v.x));
        v.y = __uint_as_float(f2tf32(v.y));
        v.z = __uint_as_float(f2tf32(v.z));
        v.w = __uint_as_float(f2tf32(v.w));
        op[i] = v;
    }
}

// ---------------------------------------------------------------------------
// Host launcher — graph-capturable
// ---------------------------------------------------------------------------
extern "C" void kernel_launch(void* const* d_in, const int* in_sizes, int n_in,
                              void* d_out, int out_size)
{
    const float* inp    = (const float*)d_in[0];
    const float* hx     = (const float*)d_in[1];
    const float* Wq1    = (const float*)d_in[3];
    const float* Wk1    = (const float*)d_in[4];
    const float* Wv1    = (const float*)d_in[5];
    const float* Wq2    = (const float*)d_in[6];
    const float* Wk2    = (const float*)d_in[7];
    const float* Wv2    = (const float*)d_in[8];
    const float* fc_w   = (const float*)d_in[9];
    const float* fc_b   = (const float*)d_in[10];
    const float* gate_w = (const float*)d_in[11];
    const float* gate_b = (const float*)d_in[12];
    const float* gru_wi = (const float*)d_in[13];
    const float* gru_wh = (const float*)d_in[14];
    const float* gru_bi = (const float*)d_in[15];
    const float* gru_bh = (const float*)d_in[16];

    float* outHx   = (float*)d_out;
    float* outMask = outHx + (long)BN * NHIDC;

    float *pkk, *pv1, *pq, *ps, *pgx, *phnr, *pqkv;
    float *pwv1r, *pwir, *pwhr, *pw2r, *pgf;
    cudaGetSymbolAddress((void**)&pkk,   g_kk);
    cudaGetSymbolAddress((void**)&pv1,   g_v1);
    cudaGetSymbolAddress((void**)&pq,    g_q);
    cudaGetSymbolAddress((void**)&ps,    g_s);
    cudaGetSymbolAddress((void**)&pgx,   g_gx);
    cudaGetSymbolAddress((void**)&phnr,  g_hnr);
    cudaGetSymbolAddress((void**)&pqkv,  g_qkv);
    cudaGetSymbolAddress((void**)&pwv1r, g_wv1r);
    cudaGetSymbolAddress((void**)&pwir,  g_wir);
    cudaGetSymbolAddress((void**)&pwhr,  g_whr);
    cudaGetSymbolAddress((void**)&pw2r,  g_w2r);
    cudaGetSymbolAddress((void**)&pgf,   g_gf);

    constexpr int SM128 = 2 * (128 * 36 + 32 * 132) * 4;   // 70656 B
    constexpr int SM64  = 2 * (128 * 36 + 32 * 68)  * 4;   // 54272 B
    constexpr int SMGRU = 2 * (32 * 36 + 32 * 388)  * 4;   // 108544 B
    constexpr int SMFIN = 2 * (128 * 36 + 32 * 68)  * 4;   // 54272 B
    cudaFuncSetAttribute(gemm_tf32<128, 2, 3, true>,  cudaFuncAttributeMaxDynamicSharedMemorySize, SM128);
    cudaFuncSetAttribute(gemm_tf32<128, 2, 1, false>, cudaFuncAttributeMaxDynamicSharedMemorySize, SM128);
    cudaFuncSetAttribute(gemm_tf32<64, 4, 0, false>,  cudaFuncAttributeMaxDynamicSharedMemorySize, SM64);
    cudaFuncSetAttribute(gemm_gru, cudaFuncAttributeMaxDynamicSharedMemorySize, SMGRU);
    cudaFuncSetAttribute(final_tc, cudaFuncAttributeMaxDynamicSharedMemorySize, SMFIN);

    // ---- weight prep (tiny) ----
    auto rnd = [](const float* s, float* d, int n) {
        round_tf32<<<(n / 4 + 255) / 256, 256>>>(s, d, n / 4);
    };
    rnd(Wv1 + 256 * 512, pwv1r, 256 * 512);
    rnd(gru_wi, pwir, 8 * 512 * 384);
    rnd(gru_wh, pwhr, 8 * 128 * 384);
    build_w2<<<(8 * 128 * 192 + 255) / 256, 256>>>(Wq2, Wk2, Wv2, pw2r);
    build_gf<<<(64 * 128 + 255) / 256, 256>>>(gate_w, fc_w, pgf);

    // ---- exact fp32 paths: kk, q ----
    gemm_tile<<<dim3(1, BN / 64, 1), 256>>>(inp, NINPC, 0, Wk1 + 256 * 64, 64, 0,
                                            pkk, 64, 0, 256);
    gemm_tile<<<dim3(1, BN / 64, 8), 256>>>(hx, NHIDC, 128, Wq1, 64, 128 * 64,
                                            pq, 512, 64, 128);

    // v1 = round(inp @ Wv1r)   (8192,256)x(256,512), A rounded in-register
    gemm_tf32<128, 2, 3, true><<<dim3(BN / 128, 4, 1), 256, SM128>>>(
        inp, 256, 0, pwv1r, 512, 0, pv1, 512, 0, 256, nullptr, nullptr, 0);

    score_mask_kernel<<<BN * 32 / 256, 256>>>();

    // gx = s*(v1 @ wi) + bi    (8192,512)x(512,384) x8
    gemm_tf32<128, 2, 1, false><<<dim3(BN / 128, 3, 8), 256, SM128>>>(
        pv1, 512, 0, pwir, 384, 512L * 384, pgx, 3072, 384, 512, ps, gru_bi, 384);

    // fused gh GEMM + GRU -> g_hn / g_hnr
    gemm_gru<<<dim3(BN / 32, 8), 256, SMGRU>>>(hx, pwhr, gru_bh);

    // qkv = hnr @ [Wq2|Wk2|Wv2] (8192,128)x(128,192) x8
    gemm_tf32<64, 4, 0, false><<<dim3(BN / 128, 3, 8), 256, SM64>>>(
        phnr, NHIDC, 128, pw2r, 192, 128L * 192, pqkv, 1536, 192, 128,
        nullptr, nullptr, 0);

    attn2_kernel<<<BN * 32 / 256, 256>>>();

    // fused final: dual tf32 GEMM + gating + masked blend + both outputs
    final_tc<<<dim3(BN * 8 / 128, 4), 256, SMFIN>>>(gate_b, fc_b, hx, outHx, outMask);

    (void)in_sizes; (void)n_in; (void)out_size;
}

// round 17
// speedup vs baseline: 1.3037x; 1.3037x over previous
#include <cuda_runtime.h>
#include <cuda_fp16.h>
#include <math.h>

#define BN    8192
#define NINPC 256
#define NHIDC 1024

// ---------------------------------------------------------------------------
// Scratch (device globals)
// ---------------------------------------------------------------------------
__device__ float g_kk  [BN * 64];
__device__ float g_q   [BN * 512];
__device__ float g_s   [BN * 8];
__device__ float g_mask[BN * 8];
__device__ float g_gx  [BN * 8 * 384];    // GRU input gates (b,z,384)
__device__ float g_hn  [BN * 1024];       // exact hx_new (pre-att)
__device__ float g_qkv [BN * 8 * 192];    // fused q2|k2|v2 (fp32 for attn2)
// half tensors
__device__ __half g_inh [BN * 256];       // inp, half
__device__ __half g_hxh [BN * 1024];      // hx, half
__device__ __half g_v1h [BN * 512];       // v1 output, half
__device__ __half g_hnh [BN * 1024];      // hx_new, half
__device__ __half g_oh  [BN * 512];       // attention-2 output, half
// half weights, transposed to (N, K) K-major
__device__ __half g_wv1h[512 * 256];
__device__ __half g_wih [8 * 384 * 512];
__device__ __half g_whh [8 * 384 * 128];
__device__ __half g_w2h [8 * 192 * 128];
__device__ __half g_gfh [256 * 64];       // interleaved [gate|fc], (n,k)

__device__ __forceinline__ unsigned smem_u32(const void* p) {
    unsigned a;
    asm("{ .reg .u64 t; cvta.to.shared.u64 t, %1; cvt.u32.u64 %0, t; }"
        : "=r"(a) : "l"(p));
    return a;
}
#define CP16(dst, src) \
    asm volatile("cp.async.cg.shared.global [%0], [%1], 16;" :: "r"(dst), "l"(src))
#define CP_COMMIT() asm volatile("cp.async.commit_group;")
#define MMA_F16(acc, a0, a1, a2, a3, b0, b1) \
    asm volatile( \
        "mma.sync.aligned.m16n8k16.row.col.f32.f16.f16.f32 " \
        "{%0,%1,%2,%3}, {%4,%5,%6,%7}, {%8,%9}, {%0,%1,%2,%3};" \
        : "+f"((acc)[0]), "+f"((acc)[1]), "+f"((acc)[2]), "+f"((acc)[3]) \
        : "r"(a0), "r"(a1), "r"(a2), "r"(a3), "r"(b0), "r"(b1))

// ---------------------------------------------------------------------------
// Prep kernels
// ---------------------------------------------------------------------------
__global__ void cvt_half(const float* __restrict__ src, __half* __restrict__ dst, int n4)
{
    int i = blockIdx.x * blockDim.x + threadIdx.x;
    if (i < n4) {
        float4 v = ((const float4*)src)[i];
        __half2* d = (__half2*)(dst + (long)i * 4);
        d[0] = __floats2half2_rn(v.x, v.y);
        d[1] = __floats2half2_rn(v.z, v.w);
    }
}

// transpose fp32 (K,N) -> half (N,K), batched over z
__global__ void build_wTh(const float* __restrict__ in, __half* __restrict__ out,
                          int K, int N, long inZ, long outZ)
{
    __shared__ float t[32][33];
    const int z = blockIdx.z;
    const int k0 = blockIdx.x * 32, n0 = blockIdx.y * 32;
    const float* iz = in + (long)z * inZ;
    __half* oz = out + (long)z * outZ;
    const int tx = threadIdx.x, ty = threadIdx.y;
#pragma unroll
    for (int i = 0; i < 32; i += 8)
        t[ty + i][tx] = iz[(long)(k0 + ty + i) * N + n0 + tx];
    __syncthreads();
#pragma unroll
    for (int i = 0; i < 32; i += 8)
        oz[(long)(n0 + ty + i) * K + k0 + tx] = __float2half_rn(t[tx][ty + i]);
}

// Wq2|Wk2|Wv2 (each (8,128,64)) -> (8, 192, 128) half, (n,k)
__global__ void build_w2h(const float* __restrict__ q, const float* __restrict__ k,
                          const float* __restrict__ v, __half* __restrict__ dst)
{
    int i = blockIdx.x * blockDim.x + threadIdx.x;
    if (i >= 8 * 192 * 128) return;
    int kk = i & 127, n = (i >> 7) % 192, z = i / (192 * 128);
    const float* src = (n < 64) ? q : ((n < 128) ? k : v);
    dst[i] = __float2half_rn(src[z * 8192 + kk * 64 + (n & 63)]);
}

// gate_w/fc_w (64x128 each) -> (256, 64) half: row n = 2c+sel, col k
__global__ void build_gfh(const float* __restrict__ gw, const float* __restrict__ fw,
                          __half* __restrict__ dst)
{
    int i = blockIdx.x * blockDim.x + threadIdx.x;
    if (i >= 256 * 64) return;
    int k = i & 63, n = i >> 6;
    int sel = n & 1, c = n >> 1;
    dst[i] = __float2half_rn((sel ? fw : gw)[k * 128 + c]);
}

// ---------------------------------------------------------------------------
// fp16 mma.sync GEMM, CTA tile 128 x NT, K-chunk 32 (2 x k16), 2-stage
// cp.async.  A (M,K) K-major half; Bt (N,K) K-major half.
// MODE 0: C=acc (fp32)   1: C=sv[m*8+z]*acc+bias (fp32)   3: C=half(acc)
// ---------------------------------------------------------------------------
template<int NT, int WARPS_M, int MODE>
__global__ void __launch_bounds__(256)
gemm_h(const __half* __restrict__ A, int lda, long aZoff,
       const __half* __restrict__ Bt, int ldbt, long bZstr,
       void* __restrict__ Cv, int ldc, long cZoff, int K,
       const float* __restrict__ sv, const float* __restrict__ bias, int biasLd)
{
    constexpr int ASTR = 40;                 // halves per row (32 + 8 pad)
    constexpr int STAGE = (128 + NT) * ASTR; // halves per stage
    constexpr int WM = 128 / WARPS_M;
    constexpr int MF = WM / 16;
    constexpr int NF = 4;
    constexpr int BITER = NT / 64;

    extern __shared__ __half smh[];
    const unsigned sbase = smem_u32(smh);

    const int tid = threadIdx.x, lane = tid & 31, wid = tid >> 5;
    const int warpM = wid % WARPS_M, warpN = wid / WARPS_M;
    const int m0 = blockIdx.x * 128, n0 = blockIdx.y * NT, z = blockIdx.z;
    const __half* Az = A + (long)z * aZoff;
    const __half* Bz = Bt + (long)z * bZstr;
    const int lr = lane >> 2, lc = lane & 3;

    float acc[MF][NF][4];
#pragma unroll
    for (int i = 0; i < MF; i++)
#pragma unroll
        for (int j = 0; j < NF; j++)
#pragma unroll
            for (int e = 0; e < 4; e++) acc[i][j][e] = 0.f;

    auto load_stage = [&](int buf, int k0) {
        const unsigned base = sbase + buf * STAGE * 2;
#pragma unroll
        for (int i = 0; i < 2; i++) {              // A: 128 rows x 4 chunks
            const int idx = i * 256 + tid;
            const int row = idx >> 2, c8 = (idx & 3) * 8;
            CP16(base + (row * ASTR + c8) * 2,
                 Az + (long)(m0 + row) * lda + k0 + c8);
        }
        const unsigned bb = base + 128 * ASTR * 2;
#pragma unroll
        for (int i = 0; i < BITER; i++) {          // B: NT rows x 4 chunks
            const int idx = i * 256 + tid;
            const int row = idx >> 2, c8 = (idx & 3) * 8;
            CP16(bb + (row * ASTR + c8) * 2,
                 Bz + (long)(n0 + row) * ldbt + k0 + c8);
        }
        CP_COMMIT();
    };

    const int NITER = K / 32;
    load_stage(0, 0);

    for (int it = 0; it < NITER; it++) {
        if (it + 1 < NITER) {
            load_stage((it + 1) & 1, (it + 1) * 32);
            asm volatile("cp.async.wait_group 1;");
        } else {
            asm volatile("cp.async.wait_group 0;");
        }
        __syncthreads();

        const __half* As = smh + (it & 1) * STAGE;
        const __half* Bs = As + 128 * ASTR;
#pragma unroll
        for (int s = 0; s < 2; s++) {
            const int k16 = s * 16;
            unsigned af[MF][4];
#pragma unroll
            for (int mf = 0; mf < MF; mf++) {
                const int r0 = warpM * WM + mf * 16 + lr;
                af[mf][0] = *(const unsigned*)&As[(r0)     * ASTR + k16 + 2 * lc];
                af[mf][1] = *(const unsigned*)&As[(r0 + 8) * ASTR + k16 + 2 * lc];
                af[mf][2] = *(const unsigned*)&As[(r0)     * ASTR + k16 + 2 * lc + 8];
                af[mf][3] = *(const unsigned*)&As[(r0 + 8) * ASTR + k16 + 2 * lc + 8];
            }
            unsigned bf[NF][2];
#pragma unroll
            for (int nf = 0; nf < NF; nf++) {
                const int cb = warpN * 32 + nf * 8 + lr;
                bf[nf][0] = *(const unsigned*)&Bs[cb * ASTR + k16 + 2 * lc];
                bf[nf][1] = *(const unsigned*)&Bs[cb * ASTR + k16 + 2 * lc + 8];
            }
#pragma unroll
            for (int mf = 0; mf < MF; mf++)
#pragma unroll
                for (int nf = 0; nf < NF; nf++)
                    MMA_F16(acc[mf][nf], af[mf][0], af[mf][1], af[mf][2], af[mf][3],
                            bf[nf][0], bf[nf][1]);
        }
        __syncthreads();
    }

    const float* bz = bias ? (bias + (long)z * biasLd) : nullptr;
#pragma unroll
    for (int mf = 0; mf < MF; mf++) {
        const int r = m0 + warpM * WM + mf * 16 + lr;
        float s0 = 1.f, s1 = 1.f;
        if (MODE == 1) { s0 = sv[(long)r * 8 + z]; s1 = sv[(long)(r + 8) * 8 + z]; }
#pragma unroll
        for (int nf = 0; nf < NF; nf++) {
            const int c = n0 + warpN * 32 + nf * 8 + lc * 2;
            float v0 = acc[mf][nf][0], v1 = acc[mf][nf][1];
            float v2 = acc[mf][nf][2], v3 = acc[mf][nf][3];
            if (MODE == 1) {
                v0 = s0 * v0 + bz[c]; v1 = s0 * v1 + bz[c + 1];
                v2 = s1 * v2 + bz[c]; v3 = s1 * v3 + bz[c + 1];
            }
            if (MODE == 3) {
                __half* Ch = (__half*)Cv + (long)z * cZoff;
                *(__half2*)(Ch + (long)r * ldc + c)       = __floats2half2_rn(v0, v1);
                *(__half2*)(Ch + (long)(r + 8) * ldc + c) = __floats2half2_rn(v2, v3);
            } else {
                float* Cz = (float*)Cv + (long)z * cZoff;
                *(float2*)(Cz + (long)r * ldc + c)       = make_float2(v0, v1);
                *(float2*)(Cz + (long)(r + 8) * ldc + c) = make_float2(v2, v3);
            }
        }
    }
}

// ---------------------------------------------------------------------------
// Fused gh GEMM (fp16) + GRU.  CTA: 32 batch rows, one z, N=384, K=128.
// A = g_hxh slice; B = g_whh (z, 384, 128).  gh staged in smem (fp32 view),
// GRU epilogue writes g_hn (fp32) and g_hnh (half).
// ---------------------------------------------------------------------------
__global__ void __launch_bounds__(256, 2)
gemm_gru_h(const float* __restrict__ hx, const float* __restrict__ bh)
{
    constexpr int ASTR = 40;
    constexpr int STAGE = (32 + 384) * ASTR;   // halves = 16640
    constexpr int GSTR = 388;                  // fp32 stride for gh staging

    extern __shared__ __half smh[];
    float* smf = reinterpret_cast<float*>(smh);
    const unsigned sbase = smem_u32(smh);

    const int tid = threadIdx.x, lane = tid & 31, wid = tid >> 5;
    const int warpM = wid & 1, warpN = wid >> 1;
    const int m0 = blockIdx.x * 32, z = blockIdx.y;
    const __half* Az = g_hxh + (long)m0 * 1024 + z * 128;
    const __half* Bz = g_whh + (long)z * 384 * 128;
    const int lr = lane >> 2, lc = lane & 3;

    float acc[12][4];
#pragma unroll
    for (int i = 0; i < 12; i++)
#pragma unroll
        for (int e = 0; e < 4; e++) acc[i][e] = 0.f;

    auto load_stage = [&](int buf, int k0) {
        const unsigned base = sbase + buf * STAGE * 2;
        if (tid < 128) {                          // A: 32 rows x 4 chunks
            const int row = tid >> 2, c8 = (tid & 3) * 8;
            CP16(base + (row * ASTR + c8) * 2, Az + (long)row * 1024 + k0 + c8);
        }
        const unsigned bb = base + 32 * ASTR * 2;
#pragma unroll
        for (int i = 0; i < 6; i++) {             // B: 384 rows x 4 chunks
            const int idx = i * 256 + tid;
            const int row = idx >> 2, c8 = (idx & 3) * 8;
            CP16(bb + (row * ASTR + c8) * 2, Bz + (long)row * 128 + k0 + c8);
        }
        CP_COMMIT();
    };

    load_stage(0, 0);
    for (int it = 0; it < 4; it++) {
        if (it < 3) {
            load_stage((it + 1) & 1, (it + 1) * 32);
            asm volatile("cp.async.wait_group 1;");
        } else {
            asm volatile("cp.async.wait_group 0;");
        }
        __syncthreads();

        const __half* As = smh + (it & 1) * STAGE;
        const __half* Bs = As + 32 * ASTR;
#pragma unroll
        for (int s = 0; s < 2; s++) {
            const int k16 = s * 16;
            const int r0 = warpM * 16 + lr;
            const unsigned a0 = *(const unsigned*)&As[(r0)     * ASTR + k16 + 2 * lc];
            const unsigned a1 = *(const unsigned*)&As[(r0 + 8) * ASTR + k16 + 2 * lc];
            const unsigned a2 = *(const unsigned*)&As[(r0)     * ASTR + k16 + 2 * lc + 8];
            const unsigned a3 = *(const unsigned*)&As[(r0 + 8) * ASTR + k16 + 2 * lc + 8];
#pragma unroll
            for (int nf = 0; nf < 12; nf++) {
                const int cb = warpN * 96 + nf * 8 + lr;
                const unsigned b0 = *(const unsigned*)&Bs[cb * ASTR + k16 + 2 * lc];
                const unsigned b1 = *(const unsigned*)&Bs[cb * ASTR + k16 + 2 * lc + 8];
                MMA_F16(acc[nf], a0, a1, a2, a3, b0, b1);
            }
        }
        __syncthreads();
    }

    // stage gh (+bias) tile into fp32 smem view [32][GSTR]
    const float* bhz = bh + z * 384;
    {
        const int r0 = warpM * 16 + lr;
#pragma unroll
        for (int nf = 0; nf < 12; nf++) {
            const int c0 = warpN * 96 + nf * 8 + lc * 2;
            const float b0 = bhz[c0], b1 = bhz[c0 + 1];
            *(float2*)(smf + (r0)     * GSTR + c0) = make_float2(acc[nf][0] + b0, acc[nf][1] + b1);
            *(float2*)(smf + (r0 + 8) * GSTR + c0) = make_float2(acc[nf][2] + b0, acc[nf][3] + b1);
        }
    }
    __syncthreads();

    // GRU epilogue
    for (int t = tid; t < 1024; t += 256) {
        const int row = t >> 5, e = (t & 31) * 4;
        const long gxb = (long)(m0 + row) * 3072 + z * 384 + e;
        const float4 xr4 = *(const float4*)(g_gx + gxb);
        const float4 xz4 = *(const float4*)(g_gx + gxb + 128);
        const float4 xn4 = *(const float4*)(g_gx + gxb + 256);
        const float4 hr4 = *(const float4*)(smf + row * GSTR + e);
        const float4 hz4 = *(const float4*)(smf + row * GSTR + e + 128);
        const float4 hn4 = *(const float4*)(smf + row * GSTR + e + 256);
        const long hb = (long)(m0 + row) * 1024 + z * 128 + e;
        const float4 h4 = *(const float4*)(hx + hb);
        const float xr[4] = {xr4.x, xr4.y, xr4.z, xr4.w};
        const float xz[4] = {xz4.x, xz4.y, xz4.z, xz4.w};
        const float xn[4] = {xn4.x, xn4.y, xn4.z, xn4.w};
        const float hr[4] = {hr4.x, hr4.y, hr4.z, hr4.w};
        const float hz[4] = {hz4.x, hz4.y, hz4.z, hz4.w};
        const float hn[4] = {hn4.x, hn4.y, hn4.z, hn4.w};
        const float hh[4] = {h4.x, h4.y, h4.z, h4.w};
        float o[4];
#pragma unroll
        for (int j = 0; j < 4; j++) {
            const float r  = 1.f / (1.f + expf(-(xr[j] + hr[j])));
            const float zz = 1.f / (1.f + expf(-(xz[j] + hz[j])));
            const float n  = tanhf(xn[j] + r * hn[j]);
            o[j] = (1.f - zz) * n + zz * hh[j];
        }
        *(float4*)(g_hn + hb) = make_float4(o[0], o[1], o[2], o[3]);
        *(__half2*)(g_hnh + hb)     = __floats2half2_rn(o[0], o[1]);
        *(__half2*)(g_hnh + hb + 2) = __floats2half2_rn(o[2], o[3]);
    }
}

// ---------------------------------------------------------------------------
// Final fp16 dual GEMM + gating + masked blend.
// A = g_oh (65536 x 64), B = g_gfh (256, 64) interleaved (2n,2n+1)=(gate,fc).
// CTA: M=128, 64 interleaved cols.  warps 4(M) x 2(N).  K=64.
// ---------------------------------------------------------------------------
__global__ void __launch_bounds__(256)
final_h(const float* __restrict__ gb, const float* __restrict__ fb,
        const float* __restrict__ hx,
        float* __restrict__ outHx, float* __restrict__ outMask)
{
    constexpr int ASTR = 40;
    constexpr int STAGE = (128 + 64) * ASTR;

    extern __shared__ __half smh[];
    const unsigned sbase = smem_u32(smh);

    const int tid = threadIdx.x, lane = tid & 31, wid = tid >> 5;
    const int warpM = wid & 3, warpN = wid >> 2;
    const int m0 = blockIdx.x * 128, n0 = blockIdx.y * 64;
    const int lr = lane >> 2, lc = lane & 3;

    float acc[2][4][4];
#pragma unroll
    for (int i = 0; i < 2; i++)
#pragma unroll
        for (int j = 0; j < 4; j++)
#pragma unroll
            for (int e = 0; e < 4; e++) acc[i][j][e] = 0.f;

    auto load_stage = [&](int buf, int k0) {
        const unsigned base = sbase + buf * STAGE * 2;
#pragma unroll
        for (int i = 0; i < 2; i++) {
            const int idx = i * 256 + tid;
            const int row = idx >> 2, c8 = (idx & 3) * 8;
            CP16(base + (row * ASTR + c8) * 2,
                 g_oh + (long)(m0 + row) * 64 + k0 + c8);
        }
        const unsigned bb = base + 128 * ASTR * 2;
        {
            const int row = tid >> 2, c8 = (tid & 3) * 8;
            CP16(bb + (row * ASTR + c8) * 2,
                 g_gfh + (long)(n0 + row) * 64 + k0 + c8);
        }
        CP_COMMIT();
    };

    load_stage(0, 0);
    for (int it = 0; it < 2; it++) {
        if (it == 0) {
            load_stage(1, 32);
            asm volatile("cp.async.wait_group 1;");
        } else {
            asm volatile("cp.async.wait_group 0;");
        }
        __syncthreads();
        const __half* As = smh + it * STAGE;
        const __half* Bs = As + 128 * ASTR;
#pragma unroll
        for (int s = 0; s < 2; s++) {
            const int k16 = s * 16;
            unsigned af[2][4];
#pragma unroll
            for (int mf = 0; mf < 2; mf++) {
                const int r0 = warpM * 32 + mf * 16 + lr;
                af[mf][0] = *(const unsigned*)&As[(r0)     * ASTR + k16 + 2 * lc];
                af[mf][1] = *(const unsigned*)&As[(r0 + 8) * ASTR + k16 + 2 * lc];
                af[mf][2] = *(const unsigned*)&As[(r0)     * ASTR + k16 + 2 * lc + 8];
                af[mf][3] = *(const unsigned*)&As[(r0 + 8) * ASTR + k16 + 2 * lc + 8];
            }
#pragma unroll
            for (int nf = 0; nf < 4; nf++) {
                const int cb = warpN * 32 + nf * 8 + lr;
                const unsigned b0 = *(const unsigned*)&Bs[cb * ASTR + k16 + 2 * lc];
                const unsigned b1 = *(const unsigned*)&Bs[cb * ASTR + k16 + 2 * lc + 8];
#pragma unroll
                for (int mf = 0; mf < 2; mf++)
                    MMA_F16(acc[mf][nf], af[mf][0], af[mf][1], af[mf][2], af[mf][3], b0, b1);
            }
        }
        __syncthreads();
    }

#pragma unroll
    for (int mf = 0; mf < 2; mf++) {
        const int r = m0 + warpM * 32 + mf * 16 + lr;
        const float ma = g_mask[r], mb = g_mask[r + 8];
#pragma unroll
        for (int nf = 0; nf < 4; nf++) {
            const int c = n0 + warpN * 32 + nf * 8 + lc * 2;
            const int n = c >> 1;
            const float gbv = gb[n], fbv = fb[n];
            {
                const float u = 1.f / (1.f + expf(-(acc[mf][nf][0] + gbv)));
                const float t = tanhf(acc[mf][nf][1] + fbv);
                const long a = (long)r * 128 + n;
                const float h2 = g_hn[a] + u * t;
                outHx[a]   = ma * h2 + (1.f - ma) * hx[a];
                outMask[a] = ma;
            }
            {
                const float u = 1.f / (1.f + expf(-(acc[mf][nf][2] + gbv)));
                const float t = tanhf(acc[mf][nf][3] + fbv);
                const long a = (long)(r + 8) * 128 + n;
                const float h2 = g_hn[a] + u * t;
                outHx[a]   = mb * h2 + (1.f - mb) * hx[a];
                outMask[a] = mb;
            }
        }
    }
}

// ---------------------------------------------------------------------------
// fp32 64x64 tiled GEMM (exact paths: kk, q) — unchanged
// ---------------------------------------------------------------------------
__global__ void gemm_tile(const float* __restrict__ A, int lda, int aZoff,
                          const float* __restrict__ Bm, int ldb, long bZstr,
                          float* __restrict__ C, int ldc, int cZoff, int K)
{
    __shared__ float As[16][68];
    __shared__ float Bs[16][64];

    const int z = blockIdx.z;
    const float* Az = A + (long)z * aZoff;
    const float* Bz = Bm + (long)z * bZstr;
    float*       Cz = C + (long)z * cZoff;

    const int m0 = blockIdx.y * 64, n0 = blockIdx.x * 64;
    const int tid = threadIdx.x;
    const int tx = tid & 15, ty = tid >> 4;
    const int arow = tid >> 2, ak = (tid & 3) << 2;
    const int bk = tid >> 4,  bn = (tid & 15) << 2;

    float acc[4][4] = {};
    for (int k0 = 0; k0 < K; k0 += 16) {
        float4 a4 = *(const float4*)(Az + (long)(m0 + arow) * lda + k0 + ak);
        float4 b4 = *(const float4*)(Bz + (long)(k0 + bk) * ldb + n0 + bn);
        __syncthreads();
        As[ak + 0][arow] = a4.x; As[ak + 1][arow] = a4.y;
        As[ak + 2][arow] = a4.z; As[ak + 3][arow] = a4.w;
        *(float4*)&Bs[bk][bn] = b4;
        __syncthreads();
#pragma unroll
        for (int kk = 0; kk < 16; kk++) {
            float4 av = *(const float4*)&As[kk][ty * 4];
            float4 bv = *(const float4*)&Bs[kk][tx * 4];
            float a_[4] = {av.x, av.y, av.z, av.w};
            float b_[4] = {bv.x, bv.y, bv.z, bv.w};
#pragma unroll
            for (int i = 0; i < 4; i++)
#pragma unroll
                for (int j = 0; j < 4; j++)
                    acc[i][j] += a_[i] * b_[j];
        }
    }
#pragma unroll
    for (int i = 0; i < 4; i++)
        *(float4*)(Cz + (long)(m0 + ty * 4 + i) * ldc + n0 + tx * 4) =
            make_float4(acc[i][0], acc[i][1], acc[i][2], acc[i][3]);
}

// ---------------------------------------------------------------------------
// score / mask — unchanged (exact fp32, rank-sensitive)
// ---------------------------------------------------------------------------
__global__ void score_mask_kernel()
{
    const int b = (blockIdx.x * blockDim.x + threadIdx.x) >> 5;
    const int lane = threadIdx.x & 31;
    const int k = lane >> 2, p = lane & 3;

    const float4* q4 = (const float4*)(g_q + (long)b * 512 + k * 64 + p * 16);
    const float4* k4 = (const float4*)(g_kk + (long)b * 64 + p * 16);
    float l = 0.f;
#pragma unroll
    for (int i = 0; i < 4; i++) {
        float4 a = q4[i], c = k4[i];
        l += a.x * c.x + a.y * c.y + a.z * c.z + a.w * c.w;
    }
    l += __shfl_xor_sync(0xFFFFFFFFu, l, 1);
    l += __shfl_xor_sync(0xFFFFFFFFu, l, 2);
    l *= 0.125f;

    int cnt = 0;
#pragma unroll
    for (int j = 0; j < 8; j++) {
        float lj = __shfl_sync(0xFFFFFFFFu, l, (j << 2) | p);
        if (lj < l || (lj == l && j < k)) cnt++;
    }
    if (p == 0) {
        g_mask[b * 8 + k] = (cnt < 4) ? 0.f : 1.f;
        g_s[b * 8 + k]    = 1.f / (1.f + expf(-l));
    }
}

// ---------------------------------------------------------------------------
// Second attention (fp32 compute, half output)
// ---------------------------------------------------------------------------
__global__ void attn2_kernel()
{
    const int b = (blockIdx.x * blockDim.x + threadIdx.x) >> 5;
    const int lane = threadIdx.x & 31;
    const int qb = lane >> 2, h = lane & 3;
    const float* base = g_qkv + (long)b * 1536;

    float4 qv[4];
    const float4* qp = (const float4*)(base + qb * 192 + h * 16);
#pragma unroll
    for (int i = 0; i < 4; i++) qv[i] = qp[i];

    float sc[8];
#pragma unroll
    for (int kb = 0; kb < 8; kb++) {
        const float4* kp = (const float4*)(base + kb * 192 + 64 + h * 16);
        float d = 0.f;
#pragma unroll
        for (int i = 0; i < 4; i++) {
            float4 kv = kp[i];
            d += qv[i].x * kv.x + qv[i].y * kv.y + qv[i].z * kv.z + qv[i].w * kv.w;
        }
        sc[kb] = d * 0.25f;
    }
    float mx = sc[0];
#pragma unroll
    for (int kb = 1; kb < 8; kb++) mx = fmaxf(mx, sc[kb]);
    float den = 0.f;
#pragma unroll
    for (int kb = 0; kb < 8; kb++) { sc[kb] = expf(sc[kb] - mx); den += sc[kb]; }
    const float inv = 1.f / den;

    float4 o[4] = {};
#pragma unroll
    for (int kb = 0; kb < 8; kb++) {
        const float4* vp = (const float4*)(base + kb * 192 + 128 + h * 16);
        const float w = sc[kb] * inv;
#pragma unroll
        for (int i = 0; i < 4; i++) {
            float4 vv = vp[i];
            o[i].x += w * vv.x; o[i].y += w * vv.y;
            o[i].z += w * vv.z; o[i].w += w * vv.w;
        }
    }
    __half* op = g_oh + (long)b * 512 + qb * 64 + h * 16;
#pragma unroll
    for (int i = 0; i < 4; i++) {
        *(__half2*)(op + i * 4)     = __floats2half2_rn(o[i].x, o[i].y);
        *(__half2*)(op + i * 4 + 2) = __floats2half2_rn(o[i].z, o[i].w);
    }
}

// ---------------------------------------------------------------------------
// Host launcher — graph-capturable
// ---------------------------------------------------------------------------
extern "C" void kernel_launch(void* const* d_in, const int* in_sizes, int n_in,
                              void* d_out, int out_size)
{
    const float* inp    = (const float*)d_in[0];
    const float* hx     = (const float*)d_in[1];
    const float* Wq1    = (const float*)d_in[3];
    const float* Wk1    = (const float*)d_in[4];
    const float* Wv1    = (const float*)d_in[5];
    const float* Wq2    = (const float*)d_in[6];
    const float* Wk2    = (const float*)d_in[7];
    const float* Wv2    = (const float*)d_in[8];
    const float* fc_w   = (const float*)d_in[9];
    const float* fc_b   = (const float*)d_in[10];
    const float* gate_w = (const float*)d_in[11];
    const float* gate_b = (const float*)d_in[12];
    const float* gru_wi = (const float*)d_in[13];
    const float* gru_wh = (const float*)d_in[14];
    const float* gru_bi = (const float*)d_in[15];
    const float* gru_bh = (const float*)d_in[16];

    float* outHx   = (float*)d_out;
    float* outMask = outHx + (long)BN * NHIDC;

    float *pkk, *pq, *ps, *pgx, *pqkv;
    __half *pinh, *phxh, *pv1h, *phnh;
    __half *pwv1h, *pwih, *pwhh, *pw2h, *pgfh;
    cudaGetSymbolAddress((void**)&pkk,   g_kk);
    cudaGetSymbolAddress((void**)&pq,    g_q);
    cudaGetSymbolAddress((void**)&ps,    g_s);
    cudaGetSymbolAddress((void**)&pgx,   g_gx);
    cudaGetSymbolAddress((void**)&pqkv,  g_qkv);
    cudaGetSymbolAddress((void**)&pinh,  g_inh);
    cudaGetSymbolAddress((void**)&phxh,  g_hxh);
    cudaGetSymbolAddress((void**)&pv1h,  g_v1h);
    cudaGetSymbolAddress((void**)&phnh,  g_hnh);
    cudaGetSymbolAddress((void**)&pwv1h, g_wv1h);
    cudaGetSymbolAddress((void**)&pwih,  g_wih);
    cudaGetSymbolAddress((void**)&pwhh,  g_whh);
    cudaGetSymbolAddress((void**)&pw2h,  g_w2h);
    cudaGetSymbolAddress((void**)&pgfh,  g_gfh);

    // dynamic smem sizes (bytes)
    constexpr int SM_G128 = 2 * (128 + 128) * 40 * 2;   // 40960
    constexpr int SM_G64  = 2 * (128 + 64)  * 40 * 2;   // 30720
    constexpr int SM_GRU  = 2 * (32 + 384)  * 40 * 2;   // 66560
    cudaFuncSetAttribute(gemm_h<128, 2, 3>, cudaFuncAttributeMaxDynamicSharedMemorySize, SM_G128);
    cudaFuncSetAttribute(gemm_h<128, 2, 1>, cudaFuncAttributeMaxDynamicSharedMemorySize, SM_G128);
    cudaFuncSetAttribute(gemm_h<64, 4, 0>,  cudaFuncAttributeMaxDynamicSharedMemorySize, SM_G64);
    cudaFuncSetAttribute(gemm_gru_h, cudaFuncAttributeMaxDynamicSharedMemorySize, SM_GRU);
    cudaFuncSetAttribute(final_h,    cudaFuncAttributeMaxDynamicSharedMemorySize, SM_G64);

    // ---- operand prep ----
    cvt_half<<<BN * 256 / 4 / 256, 256>>>(inp, pinh, BN * 256 / 4);
    cvt_half<<<BN * 1024 / 4 / 256, 256>>>(hx, phxh, BN * 1024 / 4);
    build_wTh<<<dim3(8, 16, 1), dim3(32, 8)>>>(Wv1 + 256 * 512, pwv1h, 256, 512, 0, 0);
    build_wTh<<<dim3(16, 12, 8), dim3(32, 8)>>>(gru_wi, pwih, 512, 384, 512L * 384, 384L * 512);
    build_wTh<<<dim3(4, 12, 8),  dim3(32, 8)>>>(gru_wh, pwhh, 128, 384, 128L * 384, 384L * 128);
    build_w2h<<<(8 * 192 * 128 + 255) / 256, 256>>>(Wq2, Wk2, Wv2, pw2h);
    build_gfh<<<(256 * 64 + 255) / 256, 256>>>(gate_w, fc_w, pgfh);

    // ---- exact fp32 paths: kk, q ----
    gemm_tile<<<dim3(1, BN / 64, 1), 256>>>(inp, NINPC, 0, Wk1 + 256 * 64, 64, 0,
                                            pkk, 64, 0, 256);
    gemm_tile<<<dim3(1, BN / 64, 8), 256>>>(hx, NHIDC, 128, Wq1, 64, 128 * 64,
                                            pq, 512, 64, 128);

    // v1 = half(inh @ wv1)   (8192,256)x(256,512) -> g_v1h
    gemm_h<128, 2, 3><<<dim3(BN / 128, 4, 1), 256, SM_G128>>>(
        pinh, 256, 0, pwv1h, 256, 0, pv1h, 512, 0, 256, nullptr, nullptr, 0);

    score_mask_kernel<<<BN * 32 / 256, 256>>>();

    // gx = s*(v1 @ wi) + bi   (8192,512)x(512,384) x8 -> g_gx fp32
    gemm_h<128, 2, 1><<<dim3(BN / 128, 3, 8), 256, SM_G128>>>(
        pv1h, 512, 0, pwih, 512, 384L * 512, pgx, 3072, 384, 512, ps, gru_bi, 384);

    // fused gh GEMM + GRU -> g_hn / g_hnh
    gemm_gru_h<<<dim3(BN / 32, 8), 256, SM_GRU>>>(hx, gru_bh);

    // qkv = hnh @ w2   (8192,128)x(128,192) x8 -> g_qkv fp32
    gemm_h<64, 4, 0><<<dim3(BN / 128, 3, 8), 256, SM_G64>>>(
        phnh, 1024, 128, pw2h, 128, 192L * 128, pqkv, 1536, 192, 128,
        nullptr, nullptr, 0);

    attn2_kernel<<<BN * 32 / 256, 256>>>();

    // final: dual fp16 GEMM + gating + masked blend + both outputs
    final_h<<<dim3(BN * 8 / 128, 4), 256, SM_G64>>>(gate_b, fc_b, hx, outHx, outMask);

    (void)in_sizes; (void)n_in; (void)out_size;
}